// round 6
// baseline (speedup 1.0000x reference)
#include <cuda_runtime.h>
#include <cuda_fp16.h>

// Problem-size capacities (N=100000, E=1000000 in this dataset)
#define MAXN 100352
#define MAXE 1000448
#define SCAN_BS 512
#define MAXNB ((MAXN + SCAN_BS - 1) / SCAN_BS)   // 196 <= 256
#define NBLOCKS 444                               // 148 SMs * 3 resident blocks
#define NTHREADS 512

// ---- device scratch (static: no allocations allowed) ----
__device__ int     g_deg[MAXN];           // degree, then scatter cursor; restored to 0 in agg1 phase
__device__ int     g_off[MAXN + 1];       // CSR row offsets (by dst)
__device__ int     g_bsum[MAXNB + 8];     // scan block sums
__device__ int     g_csr_src[MAXE];       // src ids grouped by dst
__device__ float   g_el1[MAXN];
__device__ float   g_er1[MAXN];
__device__ __half2 g_z1h[MAXN * 32];      // z1: N x 64 fp16 (head 0 only), 128B/node
__device__ float   g_el2[MAXN];
__device__ float   g_er2[MAXN];
__device__ __half2 g_z2h[MAXN * 16];      // z2: N x 32 fp16 (30 used), 64B/node
__device__ __align__(128) float g_part[NBLOCKS * 32];  // per-block partials (layer-2 mean)

// ---- software grid barrier (all blocks resident by construction) ----
__device__ int          g_bar_count = 0;
__device__ volatile int g_bar_gen   = 0;   // monotonic across replays; no reset needed

__device__ __forceinline__ void grid_barrier() {
    __syncthreads();
    if (threadIdx.x == 0) {
        __threadfence();
        int gen = g_bar_gen;
        if (atomicAdd(&g_bar_count, 1) == (int)gridDim.x - 1) {
            g_bar_count = 0;
            __threadfence();
            g_bar_gen = gen + 1;
        } else {
            while (g_bar_gen == gen) { }
            __threadfence();
        }
    }
    __syncthreads();
}

__global__ void __launch_bounds__(NTHREADS, 3)
k_all(const float* __restrict__ x, const float* __restrict__ feat,
      const float* __restrict__ vocab, const int* __restrict__ src,
      const int* __restrict__ dst, const float* __restrict__ W_lin1,
      const float* __restrict__ w2c, const float* __restrict__ w3c,
      const float* __restrict__ W_lin4, const float* __restrict__ W1,
      const float* __restrict__ al1, const float* __restrict__ ar1,
      const float* __restrict__ b1, const float* __restrict__ W2,
      const float* __restrict__ al2, const float* __restrict__ ar2,
      const float* __restrict__ b2, float* __restrict__ out,
      int n, int e, int nb) {
    __shared__ int   s_ws[16];
    __shared__ int   s_sb[256];
    __shared__ float s_agg[16][64];
    __shared__ float s_f[680];   // final phase: s30[0:32) hi[32:64) hv[64:136) xs[136:648) lg[648:650)

    const int t    = threadIdx.x;
    const int lane = t & 31;
    const int wib  = t >> 5;                       // warp in block (0..15)
    const int gtid = blockIdx.x * NTHREADS + t;
    const int gsz  = gridDim.x * NTHREADS;
    const int warp0  = gtid >> 5;
    const int nwarps = gsz >> 5;

    // ---------------- Phase 1: degree histogram + layer-1 node features ----------------
    for (int i = gtid; i < e; i += gsz) atomicAdd(&g_deg[dst[i]], 1);
    for (int i = gtid; i < n; i += gsz) {
        float f0 = feat[3 * i], f1 = feat[3 * i + 1], f2 = feat[3 * i + 2];
        float el = 0.f, er = 0.f;
        __half2* zo = &g_z1h[i * 32];
        #pragma unroll
        for (int q = 0; q < 32; q++) {
            int k = 2 * q;
            float za = f0 * __ldg(W1 + k)     + f1 * __ldg(W1 + 128 + k)     + f2 * __ldg(W1 + 256 + k);
            float zb = f0 * __ldg(W1 + k + 1) + f1 * __ldg(W1 + 128 + k + 1) + f2 * __ldg(W1 + 256 + k + 1);
            el += za * __ldg(al1 + k) + zb * __ldg(al1 + k + 1);
            er += za * __ldg(ar1 + k) + zb * __ldg(ar1 + k + 1);
            zo[q] = __floats2half2_rn(za, zb);
        }
        g_el1[i] = el;
        g_er1[i] = er;
    }
    grid_barrier();

    // ---------------- Phase 2: per-512-chunk exclusive scan of degrees ----------------
    for (int c = blockIdx.x; c < nb; c += gridDim.x) {
        int i = c * SCAN_BS + t;
        int v = (i < n) ? g_deg[i] : 0;
        int xv = v;
        #pragma unroll
        for (int d = 1; d < 32; d <<= 1) {
            int y = __shfl_up_sync(0xffffffffu, xv, d);
            if (lane >= d) xv += y;
        }
        if (lane == 31) s_ws[wib] = xv;
        __syncthreads();
        if (t < 16) {
            int y = s_ws[t];
            #pragma unroll
            for (int d = 1; d < 16; d <<= 1) {
                int z = __shfl_up_sync(0x0000ffffu, y, d);
                if (t >= d) y += z;
            }
            s_ws[t] = y;
        }
        __syncthreads();
        int base = (wib > 0) ? s_ws[wib - 1] : 0;
        int incl = base + xv;
        if (i < n) g_off[i] = incl - v;            // chunk-local exclusive
        if (t == SCAN_BS - 1) g_bsum[c] = incl;
        __syncthreads();
    }
    grid_barrier();

    // ---------------- Phase 3: scan block sums (redundant per block) + fixup ----------------
    if (t < 256) {
        int v = (t < nb) ? g_bsum[t] : 0;
        int xv = v;
        #pragma unroll
        for (int d = 1; d < 32; d <<= 1) {
            int y = __shfl_up_sync(0xffffffffu, xv, d);
            if (lane >= d) xv += y;
        }
        if (lane == 31) s_ws[wib] = xv;
        __syncthreads();
        if (t < 8) {
            int y = s_ws[t];
            #pragma unroll
            for (int d = 1; d < 8; d <<= 1) {
                int z = __shfl_up_sync(0x000000ffu, y, d);
                if (t >= d) y += z;
            }
            s_ws[t] = y;
        }
        __syncthreads();
        int base = (wib > 0) ? s_ws[wib - 1] : 0;
        s_sb[t] = base + xv - v;                   // exclusive prefix of chunk sums
    } else {
        __syncthreads();
        __syncthreads();
    }
    __syncthreads();
    for (int i = gtid; i < n; i += gsz) {
        int ofs = g_off[i] + s_sb[i >> 9];         // SCAN_BS == 512
        g_off[i] = ofs;
        g_deg[i] = ofs;                             // scatter cursor
    }
    if (gtid == 0) g_off[n] = e;
    grid_barrier();

    // ---------------- Phase 4: scatter src by dst ----------------
    for (int i = gtid; i < e; i += gsz) {
        int pos = atomicAdd(&g_deg[dst[i]], 1);
        g_csr_src[pos] = src[i];
    }
    grid_barrier();

    // ---------------- Phase 5: layer-1 aggregation + layer-2 node features ----------------
    for (int wid = warp0; wid < n; wid += nwarps) {
        if (lane == 0) g_deg[wid] = 0;             // restore invariant for next replay
        int o0 = g_off[wid], o1 = g_off[wid + 1];
        float ern = g_er1[wid];
        float den = 0.f, ax = 0.f, ay = 0.f;
        for (int o = o0; o < o1; o++) {
            int s = __ldg(&g_csr_src[o]);
            float ee = __ldg(&g_el1[s]) + ern;
            float w = __expf(ee > 0.f ? ee : 0.2f * ee);
            float2 z = __half22float2(__ldg(&g_z1h[s * 32 + lane]));
            den += w;
            ax += w * z.x;
            ay += w * z.y;
        }
        float inv = (o1 > o0) ? (1.0f / den) : 0.f;
        float rx = fmaxf(ax * inv + __ldg(b1 + 2 * lane), 0.f);
        float ry = fmaxf(ay * inv + __ldg(b1 + 2 * lane + 1), 0.f);
        s_agg[wib][2 * lane] = rx;
        s_agg[wib][2 * lane + 1] = ry;
        __syncwarp();
        float z2v = 0.f;
        if (lane < 30) {
            #pragma unroll
            for (int k = 0; k < 64; k++) z2v += s_agg[wib][k] * __ldg(W2 + k * 60 + lane);
        }
        float a = (lane < 30) ? z2v * __ldg(al2 + lane) : 0.f;
        float b = (lane < 30) ? z2v * __ldg(ar2 + lane) : 0.f;
        #pragma unroll
        for (int d = 16; d; d >>= 1) {
            a += __shfl_down_sync(0xffffffffu, a, d);
            b += __shfl_down_sync(0xffffffffu, b, d);
        }
        if (lane == 0) {
            g_el2[wid] = a;
            g_er2[wid] = b;
        }
        float p0 = __shfl_sync(0xffffffffu, z2v, 2 * lane);
        float p1 = __shfl_sync(0xffffffffu, z2v, 2 * lane + 1);
        if (lane < 16) g_z2h[wid * 16 + lane] = __floats2half2_rn(p0, p1);
        __syncwarp();
    }
    grid_barrier();

    // ---------------- Phase 6: layer-2 aggregation -> per-block partials ----------------
    {
        float* bs = (float*)s_f;                   // reuse final-phase smem as 32-float accum
        if (t < 32) bs[t] = 0.f;
        __syncthreads();
        float sx = 0.f, sy = 0.f;
        for (int wid = warp0; wid < n; wid += nwarps) {
            int o0 = g_off[wid], o1 = g_off[wid + 1];
            if (o0 >= o1) continue;
            float ern = g_er2[wid];
            float den = 0.f, ax = 0.f, ay = 0.f;
            for (int o = o0; o < o1; o++) {
                int s = __ldg(&g_csr_src[o]);
                float ee = __ldg(&g_el2[s]) + ern;
                float w = __expf(ee > 0.f ? ee : 0.2f * ee);
                den += w;
                if (lane < 16) {
                    float2 z = __half22float2(__ldg(&g_z2h[s * 16 + lane]));
                    ax += w * z.x;
                    ay += w * z.y;
                }
            }
            float inv = 1.0f / den;
            sx += ax * inv;
            sy += ay * inv;
        }
        if (lane < 16) {
            atomicAdd(&bs[2 * lane], sx);
            atomicAdd(&bs[2 * lane + 1], sy);
        }
        __syncthreads();
        if (t < 32) g_part[blockIdx.x * 32 + t] = bs[t];
    }
    grid_barrier();

    // ---------------- Phase 7: final (block 0 only) ----------------
    if (blockIdx.x != 0) return;
    {
        float* s30 = s_f;            // [0,32)
        float* hi  = s_f + 32;       // [32,64)
        float* hv  = s_f + 64;       // [64,136)
        float* xs  = s_f + 136;      // [136,648)
        float* lg  = s_f + 648;      // [648,650)
        if (t < 32) s30[t] = 0.f;
        xs[t] = __ldg(x + t);
        __syncthreads();
        {
            float acc = 0.f;
            int j = lane;
            for (int bb = wib; bb < (int)gridDim.x; bb += 16) acc += g_part[bb * 32 + j];
            atomicAdd(&s30[j], acc);
        }
        // h_i = W_lin1 @ x : 16 warps cover 30 rows in 2 passes
        #pragma unroll
        for (int it = 0; it < 2; it++) {
            int r = wib + 16 * it;
            if (r < 30) {
                float p = 0.f;
                for (int k = lane; k < 512; k += 32) p += xs[k] * __ldg(W_lin1 + r * 512 + k);
                #pragma unroll
                for (int d = 16; d; d >>= 1) p += __shfl_down_sync(0xffffffffu, p, d);
                if (lane == 0) hi[r] = p;
            }
        }
        __syncthreads();
        if (t < 30) {
            hv[t] = s30[t] / (float)n + b2[t];     // a[0,0]
            float h = hi[t], a = 0.f;
            for (int i2 = 0; i2 < 64; i2++) {
                float s2 = 1.f / (1.f + expf(-w2c[i2] * h));
                a += w3c[i2] * s2;
            }
            hv[30 + t] = 1.f / (1.f + expf(-a));    // h_img
        }
        if (t >= 32 && t < 42) hv[60 + (t - 32)] = vocab[t - 32];
        __syncthreads();
        if (t < 2) {
            float l = 0.f;
            for (int k = 0; k < 70; k++) l += __ldg(W_lin4 + t * 70 + k) * hv[k];
            lg[t] = l;
        }
        __syncthreads();
        if (t < 2) {
            float m = fmaxf(lg[0], lg[1]);
            float lse = m + logf(expf(lg[0] - m) + expf(lg[1] - m));
            out[t] = lg[t] - lse;
        }
    }
}

extern "C" void kernel_launch(void* const* d_in, const int* in_sizes, int n_in,
                              void* d_out, int out_size) {
    const float* x      = (const float*)d_in[0];
    const float* feat   = (const float*)d_in[1];
    const float* vocab  = (const float*)d_in[2];
    const int*   src    = (const int*)d_in[3];
    const int*   dst    = (const int*)d_in[4];
    const float* W_lin1 = (const float*)d_in[5];
    const float* w_c2   = (const float*)d_in[6];
    const float* w_c3   = (const float*)d_in[7];
    const float* W_lin4 = (const float*)d_in[8];
    const float* W1     = (const float*)d_in[9];
    const float* al1    = (const float*)d_in[10];
    const float* ar1    = (const float*)d_in[11];
    const float* b1     = (const float*)d_in[12];
    const float* W2     = (const float*)d_in[13];
    const float* al2    = (const float*)d_in[14];
    const float* ar2    = (const float*)d_in[15];
    const float* b2     = (const float*)d_in[16];

    int N = in_sizes[1] / 3;
    int E = in_sizes[3];
    int nb = (N + SCAN_BS - 1) / SCAN_BS;

    // Residency guarantee: __launch_bounds__(512, 3) caps regs so 3 blocks/SM fit;
    // verify against the actual device to stay deadlock-free.
    int sms = 148, occ = 3;
    cudaDeviceGetAttribute(&sms, cudaDevAttrMultiProcessorCount, 0);
    cudaOccupancyMaxActiveBlocksPerMultiprocessor(&occ, k_all, NTHREADS, 0);
    int nblocks = sms * occ;
    if (nblocks > NBLOCKS) nblocks = NBLOCKS;

    k_all<<<nblocks, NTHREADS>>>(x, feat, vocab, src, dst, W_lin1, w_c2, w_c3,
                                 W_lin4, W1, al1, ar1, b1, W2, al2, ar2, b2,
                                 (float*)d_out, N, E, nb);
}

// round 8
// speedup vs baseline: 1.0865x; 1.0865x over previous
#include <cuda_runtime.h>
#include <cuda_fp16.h>

// Problem-size capacities (N=100000, E=1000000 in this dataset)
#define MAXN 100352
#define MAXE 1000448
#define SCAN_BS 512
#define MAXNB ((MAXN + SCAN_BS - 1) / SCAN_BS)   // 196 <= 256
#define AGG_WARPS 8
#define NBLK2 1184                                // grid-stride blocks for fused agg2+final

// ---- device scratch (static: no allocations allowed) ----
__device__ int     g_deg[MAXN];           // degree, then scatter cursor; restored to 0 by k_agg1
__device__ int     g_off[MAXN + 1];       // CSR row offsets (by dst)
__device__ int     g_bsum[MAXNB + 8];     // scan block sums
__device__ int     g_csr_src[MAXE];       // src ids grouped by dst
__device__ float   g_w1[MAXE];            // layer-1 edge weights exp(leaky(el+er)), CSR order
__device__ float   g_w2[MAXE];            // layer-2 edge weights, CSR order
__device__ float   g_el1[MAXN];
__device__ float   g_er1[MAXN];
__device__ __half2 g_z1h[MAXN * 32];      // z1: N x 64 fp16 (head 0 only), 128B/node
__device__ float   g_el2[MAXN];
__device__ float   g_er2[MAXN];
__device__ __half2 g_z2h[MAXN * 16];      // z2: N x 32 fp16 (30 used), 64B/node
__device__ float   g_part[NBLK2 * 32];    // per-block partial sums (layer-2 mean)
__device__ int     g_done;                // last-block counter; restored to 0 each call

// -------------------- degree count + layer-1 node features (fused) --------------------
__global__ void k_pre(const int* __restrict__ dst, int e, int degBlocks,
                      const float* __restrict__ feat, const float* __restrict__ W1,
                      const float* __restrict__ al1, const float* __restrict__ ar1, int n) {
    if (blockIdx.x < degBlocks) {
        int i = blockIdx.x * blockDim.x + threadIdx.x;
        if (i < e) atomicAdd(&g_deg[dst[i]], 1);
        return;
    }
    int i = (blockIdx.x - degBlocks) * blockDim.x + threadIdx.x;
    if (i >= n) return;
    float f0 = feat[3 * i], f1 = feat[3 * i + 1], f2 = feat[3 * i + 2];
    float el = 0.f, er = 0.f;
    __half2* zo = &g_z1h[i * 32];
    #pragma unroll
    for (int q = 0; q < 32; q++) {
        int k = 2 * q;
        float za = f0 * __ldg(W1 + k)     + f1 * __ldg(W1 + 128 + k)     + f2 * __ldg(W1 + 256 + k);
        float zb = f0 * __ldg(W1 + k + 1) + f1 * __ldg(W1 + 128 + k + 1) + f2 * __ldg(W1 + 256 + k + 1);
        el += za * __ldg(al1 + k) + zb * __ldg(al1 + k + 1);
        er += za * __ldg(ar1 + k) + zb * __ldg(ar1 + k + 1);
        zo[q] = __floats2half2_rn(za, zb);
    }
    g_el1[i] = el;
    g_er1[i] = er;
}

// -------------------- scan pass 1: per-512-block exclusive scan of degrees ----------
__global__ void k_scan1(int n) {
    __shared__ int ws[16];
    int t = threadIdx.x;
    int i = blockIdx.x * SCAN_BS + t;
    int v = (i < n) ? g_deg[i] : 0;
    int x = v;
    #pragma unroll
    for (int d = 1; d < 32; d <<= 1) {
        int y = __shfl_up_sync(0xffffffffu, x, d);
        if ((t & 31) >= d) x += y;
    }
    if ((t & 31) == 31) ws[t >> 5] = x;
    __syncthreads();
    if (t < 16) {
        int y = ws[t];
        #pragma unroll
        for (int d = 1; d < 16; d <<= 1) {
            int z = __shfl_up_sync(0x0000ffffu, y, d);
            if (t >= d) y += z;
        }
        ws[t] = y;
    }
    __syncthreads();
    int base = (t >= 32) ? ws[(t >> 5) - 1] : 0;
    int incl = base + x;
    if (i < n) g_off[i] = incl - v;           // block-local exclusive
    if (t == SCAN_BS - 1) g_bsum[blockIdx.x] = incl;
}

// -------------------- scan passes 2+3 fused: every block redundantly scans bsum ----
__global__ void k_scan23(int n, int e, int nb) {
    __shared__ int sb[256];
    __shared__ int ws[8];
    int t = threadIdx.x;                       // 256 threads
    int v = (t < nb) ? g_bsum[t] : 0;
    int x = v;
    #pragma unroll
    for (int d = 1; d < 32; d <<= 1) {
        int y = __shfl_up_sync(0xffffffffu, x, d);
        if ((t & 31) >= d) x += y;
    }
    if ((t & 31) == 31) ws[t >> 5] = x;
    __syncthreads();
    if (t < 8) {
        int y = ws[t];
        #pragma unroll
        for (int d = 1; d < 8; d <<= 1) {
            int z = __shfl_up_sync(0x000000ffu, y, d);
            if (t >= d) y += z;
        }
        ws[t] = y;
    }
    __syncthreads();
    int base = (t >= 32) ? ws[(t >> 5) - 1] : 0;
    sb[t] = base + x - v;                      // exclusive prefix of block sums
    __syncthreads();
    int i = blockIdx.x * 256 + t;
    if (i < n) {
        int ofs = g_off[i] + sb[i >> 9];       // SCAN_BS == 512
        g_off[i] = ofs;
        g_deg[i] = ofs;                         // scatter cursor
    }
    if (i == 0) g_off[n] = e;
}

// -------------------- scatter + layer-1 edge weight precompute --------------------
__global__ void k_scatter(const int* __restrict__ src, const int* __restrict__ dst, int e) {
    int i = blockIdx.x * blockDim.x + threadIdx.x;
    if (i < e) {
        int s = src[i], d = dst[i];
        int pos = atomicAdd(&g_deg[d], 1);
        g_csr_src[pos] = s;
        float ee = __ldg(&g_el1[s]) + __ldg(&g_er1[d]);
        g_w1[pos] = __expf(ee > 0.f ? ee : 0.2f * ee);
    }
}

// -------------------- Layer 1 aggregation + layer 2 node features --------------------
// One warp per dst node. Weights precomputed; inner chain = csr_src -> z gather only,
// unrolled x2 for MLP. All lanes traverse the same edges: den is total in every lane.
__global__ void k_agg1(const float* __restrict__ b1, const float* __restrict__ W2,
                       const float* __restrict__ al2, const float* __restrict__ ar2, int n) {
    __shared__ float sh[AGG_WARPS][64];
    int wid = (blockIdx.x * blockDim.x + threadIdx.x) >> 5;
    int lane = threadIdx.x & 31;
    int ws_ = threadIdx.x >> 5;
    if (wid >= n) return;
    if (lane == 0) g_deg[wid] = 0;             // restore invariant for next call
    int o0 = g_off[wid], o1 = g_off[wid + 1];
    float den = 0.f, ax = 0.f, ay = 0.f;
    int o = o0;
    for (; o + 1 < o1; o += 2) {
        int   s0 = __ldg(&g_csr_src[o]);
        int   s1 = __ldg(&g_csr_src[o + 1]);
        float w0 = __ldg(&g_w1[o]);
        float w1v = __ldg(&g_w1[o + 1]);
        float2 z0 = __half22float2(__ldg(&g_z1h[s0 * 32 + lane]));
        float2 z1 = __half22float2(__ldg(&g_z1h[s1 * 32 + lane]));
        den += w0 + w1v;
        ax += w0 * z0.x + w1v * z1.x;
        ay += w0 * z0.y + w1v * z1.y;
    }
    if (o < o1) {
        int   s0 = __ldg(&g_csr_src[o]);
        float w0 = __ldg(&g_w1[o]);
        float2 z0 = __half22float2(__ldg(&g_z1h[s0 * 32 + lane]));
        den += w0;
        ax += w0 * z0.x;
        ay += w0 * z0.y;
    }
    float inv = (o1 > o0) ? (1.0f / den) : 0.f;
    float rx = fmaxf(ax * inv + __ldg(b1 + 2 * lane), 0.f);
    float ry = fmaxf(ay * inv + __ldg(b1 + 2 * lane + 1), 0.f);
    sh[ws_][2 * lane] = rx;
    sh[ws_][2 * lane + 1] = ry;
    __syncwarp();
    float z2v = 0.f;
    if (lane < 30) {
        #pragma unroll
        for (int k = 0; k < 64; k++) z2v += sh[ws_][k] * __ldg(W2 + k * 60 + lane);
    }
    float a = (lane < 30) ? z2v * __ldg(al2 + lane) : 0.f;
    float b = (lane < 30) ? z2v * __ldg(ar2 + lane) : 0.f;
    #pragma unroll
    for (int d = 16; d; d >>= 1) {
        a += __shfl_down_sync(0xffffffffu, a, d);
        b += __shfl_down_sync(0xffffffffu, b, d);
    }
    if (lane == 0) {
        g_el2[wid] = a;
        g_er2[wid] = b;
    }
    float p0 = __shfl_sync(0xffffffffu, z2v, 2 * lane);
    float p1 = __shfl_sync(0xffffffffu, z2v, 2 * lane + 1);
    if (lane < 16) g_z2h[wid * 16 + lane] = __floats2half2_rn(p0, p1);
}

// -------------------- Layer 2 edge weight precompute --------------------
// Warp per dst node; lanes independent over edges (MLP=32 on el2 gathers).
__global__ void k_w2(int n) {
    int wid = (blockIdx.x * blockDim.x + threadIdx.x) >> 5;
    int lane = threadIdx.x & 31;
    if (wid >= n) return;
    int o0 = g_off[wid], o1 = g_off[wid + 1];
    float ern = g_er2[wid];
    for (int o = o0 + lane; o < o1; o += 32) {
        int s = __ldg(&g_csr_src[o]);
        float ee = __ldg(&g_el2[s]) + ern;
        g_w2[o] = __expf(ee > 0.f ? ee : 0.2f * ee);
    }
}

// -------------------- Layer 2 aggregation + final (fused, last-block pattern) -------
// All lanes traverse the same edges: den is the full sum in every lane (NO cross-lane
// reduction — that was the R7 bug).
__global__ void k_agg2f(int n,
                        const float* __restrict__ x, const float* __restrict__ vocab,
                        const float* __restrict__ W_lin1, const float* __restrict__ w2c,
                        const float* __restrict__ w3c, const float* __restrict__ W_lin4,
                        const float* __restrict__ b2, float* __restrict__ out) {
    __shared__ float bs[32];
    int t = threadIdx.x;                       // 256 threads
    int lane = t & 31;
    if (t < 32) bs[t] = 0.f;
    __syncthreads();
    int warp0 = (blockIdx.x * blockDim.x + t) >> 5;
    int nwarps = (gridDim.x * blockDim.x) >> 5;
    float sx = 0.f, sy = 0.f;
    for (int wid = warp0; wid < n; wid += nwarps) {
        int o0 = g_off[wid], o1 = g_off[wid + 1];
        if (o0 >= o1) continue;
        float den = 0.f, ax = 0.f, ay = 0.f;
        int o = o0;
        for (; o + 1 < o1; o += 2) {
            int   s0 = __ldg(&g_csr_src[o]);
            int   s1 = __ldg(&g_csr_src[o + 1]);
            float w0 = __ldg(&g_w2[o]);
            float w1v = __ldg(&g_w2[o + 1]);
            den += w0 + w1v;
            if (lane < 16) {
                float2 z0 = __half22float2(__ldg(&g_z2h[s0 * 16 + lane]));
                float2 z1 = __half22float2(__ldg(&g_z2h[s1 * 16 + lane]));
                ax += w0 * z0.x + w1v * z1.x;
                ay += w0 * z0.y + w1v * z1.y;
            }
        }
        if (o < o1) {
            int   s0 = __ldg(&g_csr_src[o]);
            float w0 = __ldg(&g_w2[o]);
            den += w0;
            if (lane < 16) {
                float2 z0 = __half22float2(__ldg(&g_z2h[s0 * 16 + lane]));
                ax += w0 * z0.x;
                ay += w0 * z0.y;
            }
        }
        float inv = 1.0f / den;                // den already total per lane
        sx += ax * inv;
        sy += ay * inv;
    }
    if (lane < 16) {
        atomicAdd(&bs[2 * lane], sx);
        atomicAdd(&bs[2 * lane + 1], sy);
    }
    __syncthreads();
    if (t < 32) g_part[blockIdx.x * 32 + t] = bs[t];
    __threadfence();
    __shared__ int amLast;
    if (t == 0) amLast = (atomicAdd(&g_done, 1) == (int)gridDim.x - 1);
    __syncthreads();
    if (!amLast) return;

    // ---------------- final phase (single block, 256 threads) ----------------
    if (t == 0) g_done = 0;                    // restore invariant for next call
    __shared__ float s30[32];
    __shared__ float hi[32];
    __shared__ float hv[72];
    __shared__ float xs[512];
    __shared__ float lg[2];
    if (t < 32) s30[t] = 0.f;
    xs[t] = __ldg(x + t);
    xs[t + 256] = __ldg(x + t + 256);
    __syncthreads();
    {
        float acc = 0.f;
        int j = t & 31;
        for (int bb = t >> 5; bb < (int)gridDim.x; bb += 8) acc += g_part[bb * 32 + j];
        atomicAdd(&s30[j], acc);
    }
    int w8 = t >> 5;
    #pragma unroll
    for (int it = 0; it < 4; it++) {
        int r = w8 + 8 * it;
        if (r < 30) {
            float p = 0.f;
            for (int k = lane; k < 512; k += 32) p += xs[k] * __ldg(W_lin1 + r * 512 + k);
            #pragma unroll
            for (int d = 16; d; d >>= 1) p += __shfl_down_sync(0xffffffffu, p, d);
            if (lane == 0) hi[r] = p;
        }
    }
    __syncthreads();
    if (t < 30) {
        hv[t] = s30[t] / (float)n + b2[t];     // a[0,0]
        float h = hi[t], a = 0.f;
        for (int i2 = 0; i2 < 64; i2++) {
            float s2 = 1.f / (1.f + expf(-w2c[i2] * h));
            a += w3c[i2] * s2;
        }
        hv[30 + t] = 1.f / (1.f + expf(-a));    // h_img
    }
    if (t >= 32 && t < 42) hv[60 + (t - 32)] = vocab[t - 32];
    __syncthreads();
    if (t < 2) {
        float l = 0.f;
        for (int k = 0; k < 70; k++) l += __ldg(W_lin4 + t * 70 + k) * hv[k];
        lg[t] = l;
    }
    __syncthreads();
    if (t < 2) {
        float m = fmaxf(lg[0], lg[1]);
        float lse = m + logf(expf(lg[0] - m) + expf(lg[1] - m));
        out[t] = lg[t] - lse;
    }
}

extern "C" void kernel_launch(void* const* d_in, const int* in_sizes, int n_in,
                              void* d_out, int out_size) {
    const float* x      = (const float*)d_in[0];
    const float* feat   = (const float*)d_in[1];
    const float* vocab  = (const float*)d_in[2];
    const int*   src    = (const int*)d_in[3];
    const int*   dst    = (const int*)d_in[4];
    const float* W_lin1 = (const float*)d_in[5];
    const float* w_c2   = (const float*)d_in[6];
    const float* w_c3   = (const float*)d_in[7];
    const float* W_lin4 = (const float*)d_in[8];
    const float* W1     = (const float*)d_in[9];
    const float* al1    = (const float*)d_in[10];
    const float* ar1    = (const float*)d_in[11];
    const float* b1     = (const float*)d_in[12];
    const float* W2     = (const float*)d_in[13];
    const float* al2    = (const float*)d_in[14];
    const float* ar2    = (const float*)d_in[15];
    const float* b2     = (const float*)d_in[16];

    int N = in_sizes[1] / 3;
    int E = in_sizes[3];
    int nb = (N + SCAN_BS - 1) / SCAN_BS;
    int degBlocks  = (E + 255) / 256;
    int nodeBlocks = (N + 255) / 256;
    int aggblk = (N + AGG_WARPS - 1) / AGG_WARPS;

    k_pre<<<degBlocks + nodeBlocks, 256>>>(dst, E, degBlocks, feat, W1, al1, ar1, N);
    k_scan1<<<nb, SCAN_BS>>>(N);
    k_scan23<<<(N + 255) / 256, 256>>>(N, E, nb);
    k_scatter<<<(E + 255) / 256, 256>>>(src, dst, E);
    k_agg1<<<aggblk, AGG_WARPS * 32>>>(b1, W2, al2, ar2, N);
    k_w2<<<aggblk, AGG_WARPS * 32>>>(N);
    k_agg2f<<<NBLK2, AGG_WARPS * 32>>>(N, x, vocab, W_lin1, w_c2, w_c3, W_lin4, b2, (float*)d_out);
}

// round 10
// speedup vs baseline: 1.2621x; 1.1617x over previous
#include <cuda_runtime.h>
#include <cuda_fp16.h>

// Problem-size capacities (N=100000, E=1000000 in this dataset)
#define MAXN 100352
#define MAXE 1000448
#define SCAN_BS 512
#define MAXNB ((MAXN + SCAN_BS - 1) / SCAN_BS)   // 196 <= 256
#define AGG_WARPS 8
#define NBLK2 1184                                // grid-stride blocks for k_agg2 (148*8)

// ---- device scratch (static: no allocations allowed) ----
__device__ int     g_deg[MAXN];           // degree, then scatter cursor
__device__ int     g_off[MAXN + 1];       // CSR row offsets (by dst)
__device__ int     g_bsum[MAXNB + 8];     // scan block sums
__device__ int     g_csr_src[MAXE];       // src ids grouped by dst
__device__ float   g_el1[MAXN];
__device__ float   g_er1[MAXN];
__device__ __half2 g_z1h[MAXN * 32];      // z1: N x 64 fp16 (head 0 only), 128B/node
__device__ float   g_el2[MAXN];
__device__ float   g_er2[MAXN];
__device__ __half2 g_z2h[MAXN * 16];      // z2: N x 32 fp16 (30 used), 64B/node
__device__ float   g_part[NBLK2 * 32];    // per-block partial sums (layer-2 mean)

// -------------------- degree count + layer-1 node features (fused) --------------------
__global__ void k_deg_node1(const int* __restrict__ dst, int e, int degBlocks,
                            const float* __restrict__ feat, const float* __restrict__ W1,
                            const float* __restrict__ al1, const float* __restrict__ ar1, int n) {
    if (blockIdx.x < degBlocks) {
        int i = blockIdx.x * blockDim.x + threadIdx.x;
        if (i < e) atomicAdd(&g_deg[dst[i]], 1);
        return;
    }
    int i = (blockIdx.x - degBlocks) * blockDim.x + threadIdx.x;
    if (i >= n) return;
    float f0 = feat[3 * i], f1 = feat[3 * i + 1], f2 = feat[3 * i + 2];
    float el = 0.f, er = 0.f;
    __half2* zo = &g_z1h[i * 32];
    #pragma unroll
    for (int q = 0; q < 32; q++) {
        int k = 2 * q;
        float za = f0 * __ldg(W1 + k)     + f1 * __ldg(W1 + 128 + k)     + f2 * __ldg(W1 + 256 + k);
        float zb = f0 * __ldg(W1 + k + 1) + f1 * __ldg(W1 + 128 + k + 1) + f2 * __ldg(W1 + 256 + k + 1);
        el += za * __ldg(al1 + k) + zb * __ldg(al1 + k + 1);
        er += za * __ldg(ar1 + k) + zb * __ldg(ar1 + k + 1);
        zo[q] = __floats2half2_rn(za, zb);
    }
    g_el1[i] = el;
    g_er1[i] = er;
}

// -------------------- scan pass 1 (shuffle-based) --------------------
__global__ void k_scan1(int n) {
    __shared__ int ws[16];
    int t = threadIdx.x;
    int i = blockIdx.x * SCAN_BS + t;
    int v = (i < n) ? g_deg[i] : 0;
    int x = v;
    #pragma unroll
    for (int d = 1; d < 32; d <<= 1) {
        int y = __shfl_up_sync(0xffffffffu, x, d);
        if ((t & 31) >= d) x += y;
    }
    if ((t & 31) == 31) ws[t >> 5] = x;
    __syncthreads();
    if (t < 16) {
        int y = ws[t];
        #pragma unroll
        for (int d = 1; d < 16; d <<= 1) {
            int z = __shfl_up_sync(0x0000ffffu, y, d);
            if (t >= d) y += z;
        }
        ws[t] = y;
    }
    __syncthreads();
    int base = (t >= 32) ? ws[(t >> 5) - 1] : 0;
    int incl = base + x;
    if (i < n) g_off[i] = incl - v;           // block-local exclusive
    if (t == SCAN_BS - 1) g_bsum[blockIdx.x] = incl;
}

// -------------------- scan passes 2+3 fused: every block redundantly scans bsum ----
__global__ void k_scan23(int n, int e, int nb) {
    __shared__ int sb[256];
    __shared__ int ws[8];
    int t = threadIdx.x;                       // 256 threads
    int v = (t < nb) ? g_bsum[t] : 0;
    int x = v;
    #pragma unroll
    for (int d = 1; d < 32; d <<= 1) {
        int y = __shfl_up_sync(0xffffffffu, x, d);
        if ((t & 31) >= d) x += y;
    }
    if ((t & 31) == 31) ws[t >> 5] = x;
    __syncthreads();
    if (t < 8) {
        int y = ws[t];
        #pragma unroll
        for (int d = 1; d < 8; d <<= 1) {
            int z = __shfl_up_sync(0x000000ffu, y, d);
            if (t >= d) y += z;
        }
        ws[t] = y;
    }
    __syncthreads();
    int base = (t >= 32) ? ws[(t >> 5) - 1] : 0;
    sb[t] = base + x - v;                      // exclusive prefix of block sums
    __syncthreads();
    int i = blockIdx.x * 256 + t;
    if (i < n) {
        int ofs = g_off[i] + sb[i >> 9];       // SCAN_BS == 512
        g_off[i] = ofs;
        g_deg[i] = ofs;                         // scatter cursor
    }
    if (i == 0) g_off[n] = e;
}

__global__ void k_scatter(const int* __restrict__ src, const int* __restrict__ dst, int e) {
    int i = blockIdx.x * blockDim.x + threadIdx.x;
    if (i < e) {
        int pos = atomicAdd(&g_deg[dst[i]], 1);
        g_csr_src[pos] = src[i];
    }
}

// -------------------- Layer 1 aggregation + layer 2 node features --------------------
// One warp per dst node; inline exp; inner loop unrolled x2 for load MLP.
__global__ void k_agg1(const float* __restrict__ b1, const float* __restrict__ W2,
                       const float* __restrict__ al2, const float* __restrict__ ar2, int n) {
    __shared__ float sh[AGG_WARPS][64];
    int wid = (blockIdx.x * blockDim.x + threadIdx.x) >> 5;
    int lane = threadIdx.x & 31;
    int ws = threadIdx.x >> 5;
    if (wid >= n) return;
    int o0 = g_off[wid], o1 = g_off[wid + 1];
    float ern = g_er1[wid];
    float den = 0.f, ax = 0.f, ay = 0.f;
    int o = o0;
    for (; o + 1 < o1; o += 2) {
        int s0 = __ldg(&g_csr_src[o]);
        int s1 = __ldg(&g_csr_src[o + 1]);
        float e0 = __ldg(&g_el1[s0]) + ern;
        float e1 = __ldg(&g_el1[s1]) + ern;
        float2 z0 = __half22float2(__ldg(&g_z1h[s0 * 32 + lane]));
        float2 z1 = __half22float2(__ldg(&g_z1h[s1 * 32 + lane]));
        float w0 = __expf(e0 > 0.f ? e0 : 0.2f * e0);
        float w1 = __expf(e1 > 0.f ? e1 : 0.2f * e1);
        den += w0 + w1;
        ax += w0 * z0.x + w1 * z1.x;
        ay += w0 * z0.y + w1 * z1.y;
    }
    if (o < o1) {
        int s0 = __ldg(&g_csr_src[o]);
        float e0 = __ldg(&g_el1[s0]) + ern;
        float2 z0 = __half22float2(__ldg(&g_z1h[s0 * 32 + lane]));
        float w0 = __expf(e0 > 0.f ? e0 : 0.2f * e0);
        den += w0;
        ax += w0 * z0.x;
        ay += w0 * z0.y;
    }
    float inv = (o1 > o0) ? (1.0f / den) : 0.f;
    float rx = fmaxf(ax * inv + __ldg(b1 + 2 * lane), 0.f);
    float ry = fmaxf(ay * inv + __ldg(b1 + 2 * lane + 1), 0.f);
    sh[ws][2 * lane] = rx;
    sh[ws][2 * lane + 1] = ry;
    __syncwarp();
    float z2v = 0.f;
    if (lane < 30) {
        #pragma unroll
        for (int k = 0; k < 64; k++) z2v += sh[ws][k] * __ldg(W2 + k * 60 + lane);
    }
    float a = (lane < 30) ? z2v * __ldg(al2 + lane) : 0.f;
    float b = (lane < 30) ? z2v * __ldg(ar2 + lane) : 0.f;
    #pragma unroll
    for (int d = 16; d; d >>= 1) {
        a += __shfl_down_sync(0xffffffffu, a, d);
        b += __shfl_down_sync(0xffffffffu, b, d);
    }
    if (lane == 0) {
        g_el2[wid] = a;
        g_er2[wid] = b;
    }
    float p0 = __shfl_sync(0xffffffffu, z2v, 2 * lane);
    float p1 = __shfl_sync(0xffffffffu, z2v, 2 * lane + 1);
    if (lane < 16) g_z2h[wid * 16 + lane] = __floats2half2_rn(p0, p1);
}

// -------------------- Layer 2 aggregation -> global mean partials --------------------
// Grid-stride over nodes; inline exp; inner loop unrolled x2.
__global__ void k_agg2(int n) {
    __shared__ float bs[32];
    int t = threadIdx.x;
    if (t < 32) bs[t] = 0.f;
    __syncthreads();
    int lane = t & 31;
    int warp0 = (blockIdx.x * blockDim.x + t) >> 5;
    int nwarps = (gridDim.x * blockDim.x) >> 5;
    float sx = 0.f, sy = 0.f;
    for (int wid = warp0; wid < n; wid += nwarps) {
        int o0 = g_off[wid], o1 = g_off[wid + 1];
        if (o0 >= o1) continue;
        float ern = g_er2[wid];
        float den = 0.f, ax = 0.f, ay = 0.f;
        int o = o0;
        for (; o + 1 < o1; o += 2) {
            int s0 = __ldg(&g_csr_src[o]);
            int s1 = __ldg(&g_csr_src[o + 1]);
            float e0 = __ldg(&g_el2[s0]) + ern;
            float e1 = __ldg(&g_el2[s1]) + ern;
            float w0 = __expf(e0 > 0.f ? e0 : 0.2f * e0);
            float w1 = __expf(e1 > 0.f ? e1 : 0.2f * e1);
            den += w0 + w1;
            if (lane < 16) {
                float2 z0 = __half22float2(__ldg(&g_z2h[s0 * 16 + lane]));
                float2 z1 = __half22float2(__ldg(&g_z2h[s1 * 16 + lane]));
                ax += w0 * z0.x + w1 * z1.x;
                ay += w0 * z0.y + w1 * z1.y;
            }
        }
        if (o < o1) {
            int s0 = __ldg(&g_csr_src[o]);
            float e0 = __ldg(&g_el2[s0]) + ern;
            float w0 = __expf(e0 > 0.f ? e0 : 0.2f * e0);
            den += w0;
            if (lane < 16) {
                float2 z0 = __half22float2(__ldg(&g_z2h[s0 * 16 + lane]));
                ax += w0 * z0.x;
                ay += w0 * z0.y;
            }
        }
        float inv = 1.0f / den;
        sx += ax * inv;
        sy += ay * inv;
    }
    if (lane < 16) {
        atomicAdd(&bs[2 * lane], sx);
        atomicAdd(&bs[2 * lane + 1], sy);
    }
    __syncthreads();
    if (t < 32) g_part[blockIdx.x * 32 + t] = bs[t];
}

// -------------------- Final: reduce partials + scalar tail + log_softmax --------------------
__global__ void k_final(const float* __restrict__ x, const float* __restrict__ vocab,
                        const float* __restrict__ W_lin1, const float* __restrict__ w2c,
                        const float* __restrict__ w3c, const float* __restrict__ W_lin4,
                        const float* __restrict__ b2, float* __restrict__ out,
                        int n, int nparts) {
    __shared__ float s30[32];
    __shared__ float hi[32];
    __shared__ float hv[72];
    __shared__ float xs[512];
    __shared__ float lg[2];
    int t = threadIdx.x;
    if (t < 32) s30[t] = 0.f;
    if (t < 512) xs[t] = x[t];
    __syncthreads();
    // reduce g_part[nparts][32]
    {
        float acc = 0.f;
        int j = t & 31;
        for (int bb = t >> 5; bb < nparts; bb += 32) acc += g_part[bb * 32 + j];
        atomicAdd(&s30[j], acc);
    }
    // h_i = W_lin1 @ x : one warp per output row
    int w = t >> 5, lane = t & 31;
    if (w < 30) {
        float p = 0.f;
        for (int k = lane; k < 512; k += 32) p += xs[k] * __ldg(W_lin1 + w * 512 + k);
        #pragma unroll
        for (int d = 16; d; d >>= 1) p += __shfl_down_sync(0xffffffffu, p, d);
        if (lane == 0) hi[w] = p;
    }
    __syncthreads();
    if (t < 30) {
        hv[t] = s30[t] / (float)n + b2[t];            // a[0,0]
        float h = hi[t], a = 0.f;
        for (int i2 = 0; i2 < 64; i2++) {
            float s2 = 1.f / (1.f + expf(-w2c[i2] * h));
            a += w3c[i2] * s2;
        }
        hv[30 + t] = 1.f / (1.f + expf(-a));           // h_img
    }
    if (t >= 32 && t < 42) hv[60 + (t - 32)] = vocab[t - 32];
    __syncthreads();
    if (t < 2) {
        float l = 0.f;
        for (int k = 0; k < 70; k++) l += __ldg(W_lin4 + t * 70 + k) * hv[k];
        lg[t] = l;
    }
    __syncthreads();
    if (t < 2) {
        float m = fmaxf(lg[0], lg[1]);
        float lse = m + logf(expf(lg[0] - m) + expf(lg[1] - m));
        out[t] = lg[t] - lse;
    }
}

extern "C" void kernel_launch(void* const* d_in, const int* in_sizes, int n_in,
                              void* d_out, int out_size) {
    const float* x      = (const float*)d_in[0];
    const float* feat   = (const float*)d_in[1];
    const float* vocab  = (const float*)d_in[2];
    const int*   src    = (const int*)d_in[3];
    const int*   dst    = (const int*)d_in[4];
    const float* W_lin1 = (const float*)d_in[5];
    const float* w_c2   = (const float*)d_in[6];
    const float* w_c3   = (const float*)d_in[7];
    const float* W_lin4 = (const float*)d_in[8];
    const float* W1     = (const float*)d_in[9];
    const float* al1    = (const float*)d_in[10];
    const float* ar1    = (const float*)d_in[11];
    const float* b1     = (const float*)d_in[12];
    const float* W2     = (const float*)d_in[13];
    const float* al2    = (const float*)d_in[14];
    const float* ar2    = (const float*)d_in[15];
    const float* b2     = (const float*)d_in[16];

    int N = in_sizes[1] / 3;
    int E = in_sizes[3];
    int nb = (N + SCAN_BS - 1) / SCAN_BS;
    int degBlocks  = (E + 255) / 256;
    int nodeBlocks = (N + 255) / 256;
    int aggblk = (N + AGG_WARPS - 1) / AGG_WARPS;

    void* degPtr = nullptr;
    cudaGetSymbolAddress(&degPtr, g_deg);
    cudaMemsetAsync(degPtr, 0, (size_t)N * sizeof(int), 0);

    k_deg_node1<<<degBlocks + nodeBlocks, 256>>>(dst, E, degBlocks, feat, W1, al1, ar1, N);
    k_scan1<<<nb, SCAN_BS>>>(N);
    k_scan23<<<(N + 255) / 256, 256>>>(N, E, nb);
    k_scatter<<<(E + 255) / 256, 256>>>(src, dst, E);
    k_agg1<<<aggblk, AGG_WARPS * 32>>>(b1, W2, al2, ar2, N);
    k_agg2<<<NBLK2, AGG_WARPS * 32>>>(N);
    k_final<<<1, 1024>>>(x, vocab, W_lin1, w_c2, w_c3, W_lin4, b2, (float*)d_out, N, NBLK2);
}

// round 11
// speedup vs baseline: 1.5622x; 1.2377x over previous
#include <cuda_runtime.h>

// Problem-size capacities (N=100000, E=1000000 in this dataset)
#define MAXN 100352
#define MAXE 1000448
#define NBLK3 592            // 148 SMs * 4, node3 grid

// ---- device scratch (static: no allocations allowed) ----
__device__ float4 g_f4[MAXN];          // (f0, f1, f2, el1) per node
__device__ float  g_er1[MAXN];
// zeroed each call by one memset: [0,4N) layer1 accum (den,a0,a1,a2)*N ; [4N,5N) den2 ; [5N,6N) C
__device__ float  g_zbuf[6 * MAXN];
__device__ float  g_z2[MAXN * 32];     // z2: N x 32 (30 used), coalesced rows
__device__ float  g_el2[MAXN];
__device__ float  g_er2[MAXN];
__device__ float  g_part[NBLK3 * 32];  // per-block partials
__device__ int    g_done;              // last-block counter; self-resetting

// -------- node pass 1: el1/er1 via collapsed 3-vectors cl = W1@al1, cr = W1@ar1 --------
__global__ void k_node1(const float* __restrict__ feat, const float* __restrict__ W1,
                        const float* __restrict__ al1, const float* __restrict__ ar1, int n) {
    __shared__ float sc[6];   // cl0,cr0,cl1,cr1,cl2,cr2
    int t = threadIdx.x, lane = t & 31;
    if (t < 192) {
        int which = t >> 5;              // 0..5
        int j = which >> 1;              // feat dim
        const float* a = (which & 1) ? ar1 : al1;
        float p = __ldg(W1 + j * 128 + lane) * __ldg(a + lane)
                + __ldg(W1 + j * 128 + lane + 32) * __ldg(a + lane + 32);
        #pragma unroll
        for (int d = 16; d; d >>= 1) p += __shfl_down_sync(0xffffffffu, p, d);
        if (lane == 0) sc[which] = p;
    }
    __syncthreads();
    int i = blockIdx.x * blockDim.x + t;
    if (i >= n) return;
    float f0 = feat[3 * i], f1 = feat[3 * i + 1], f2 = feat[3 * i + 2];
    float el = f0 * sc[0] + f1 * sc[2] + f2 * sc[4];
    float er = f0 * sc[1] + f1 * sc[3] + f2 * sc[5];
    g_f4[i] = make_float4(f0, f1, f2, el);
    g_er1[i] = er;
}

// -------- edge pass 1: den1[dst] += w ; acc[dst] += w * feat[src]  (4 REDs/edge) --------
__global__ void k_edge1(const int* __restrict__ src, const int* __restrict__ dst, int e) {
    int i = blockIdx.x * blockDim.x + threadIdx.x;
    if (i >= e) return;
    int s = src[i], d = dst[i];
    float4 fs = __ldg(&g_f4[s]);
    float ee = fs.w + __ldg(&g_er1[d]);
    float w = __expf(ee > 0.f ? ee : 0.2f * ee);
    float* A = g_zbuf + 4 * d;
    atomicAdd(A,     w);
    atomicAdd(A + 1, w * fs.x);
    atomicAdd(A + 2, w * fs.y);
    atomicAdd(A + 3, w * fs.z);
}

// -------- node pass 2: h1 = acc/den ; r1 = relu(h1@W1 + b1) ; z2 = r1@W2 ; el2/er2 --------
__global__ void k_node2(const float* __restrict__ W1, const float* __restrict__ b1,
                        const float* __restrict__ W2, const float* __restrict__ al2,
                        const float* __restrict__ ar2, int n) {
    int i = blockIdx.x * blockDim.x + threadIdx.x;
    if (i >= n) return;
    const float4 A = *(const float4*)(g_zbuf + 4 * i);
    float inv = (A.x > 0.f) ? (1.f / A.x) : 0.f;
    float h0 = A.y * inv, h1 = A.z * inv, h2 = A.w * inv;
    float z2[30];
    #pragma unroll
    for (int j = 0; j < 30; j++) z2[j] = 0.f;
    for (int k = 0; k < 64; k++) {
        float r = h0 * __ldg(W1 + k) + h1 * __ldg(W1 + 128 + k) + h2 * __ldg(W1 + 256 + k)
                + __ldg(b1 + k);
        r = fmaxf(r, 0.f);
        const float* w2row = W2 + k * 60;
        #pragma unroll
        for (int j = 0; j < 30; j++) z2[j] += r * __ldg(w2row + j);
    }
    float el2 = 0.f, er2 = 0.f;
    float* zo = g_z2 + i * 32;
    #pragma unroll
    for (int j = 0; j < 30; j++) {
        zo[j] = z2[j];
        el2 += z2[j] * __ldg(al2 + j);
        er2 += z2[j] * __ldg(ar2 + j);
    }
    zo[30] = 0.f;
    zo[31] = 0.f;
    g_el2[i] = el2;
    g_er2[i] = er2;
}

// -------- edge pass 2: den2[dst] += w2 --------
__global__ void k_edge2(const int* __restrict__ src, const int* __restrict__ dst, int e) {
    int i = blockIdx.x * blockDim.x + threadIdx.x;
    if (i >= e) return;
    int s = src[i], d = dst[i];
    float ee = __ldg(&g_el2[s]) + __ldg(&g_er2[d]);
    float w = __expf(ee > 0.f ? ee : 0.2f * ee);
    atomicAdd(g_zbuf + 4 * MAXN + d, w);
}

// -------- edge pass 3: C[src] += w2 / den2[dst] --------
__global__ void k_edge3(const int* __restrict__ src, const int* __restrict__ dst, int e) {
    int i = blockIdx.x * blockDim.x + threadIdx.x;
    if (i >= e) return;
    int s = src[i], d = dst[i];
    float ee = __ldg(&g_el2[s]) + __ldg(&g_er2[d]);
    float w = __expf(ee > 0.f ? ee : 0.2f * ee);
    float den = __ldg(g_zbuf + 4 * MAXN + d);   // >= w > 0 since this edge contributed
    atomicAdd(g_zbuf + 5 * MAXN + s, w / den);
}

// -------- node pass 3 + final: sum_s C[s]*z2[s] (lane-locked components), then tail ----
__global__ void k_node3f(int n,
                         const float* __restrict__ x, const float* __restrict__ vocab,
                         const float* __restrict__ W_lin1, const float* __restrict__ w2c,
                         const float* __restrict__ w3c, const float* __restrict__ W_lin4,
                         const float* __restrict__ b2, float* __restrict__ out) {
    __shared__ float bs[32];
    int t = threadIdx.x, lane = t & 31;
    if (t < 32) bs[t] = 0.f;
    __syncthreads();
    const float* C = g_zbuf + 5 * MAXN;
    float acc = 0.f;
    int total = n * 32;
    // stride is a multiple of 32 -> each lane keeps a fixed component j = lane
    for (int i = blockIdx.x * blockDim.x + t; i < total; i += gridDim.x * blockDim.x) {
        int s = i >> 5;
        acc += __ldg(C + s) * __ldg(g_z2 + i);
    }
    atomicAdd(&bs[lane], acc);
    __syncthreads();
    if (t < 32) g_part[blockIdx.x * 32 + t] = bs[t];
    __threadfence();
    __shared__ int amLast;
    if (t == 0) amLast = (atomicAdd(&g_done, 1) == (int)gridDim.x - 1);
    __syncthreads();
    if (!amLast) return;

    // ---------------- final phase (single block, 256 threads) ----------------
    if (t == 0) g_done = 0;                    // restore invariant for next replay
    __shared__ float s30[32];
    __shared__ float hi[32];
    __shared__ float hv[72];
    __shared__ float xs[512];
    __shared__ float lg[2];
    if (t < 32) s30[t] = 0.f;
    xs[t] = __ldg(x + t);
    xs[t + 256] = __ldg(x + t + 256);
    __syncthreads();
    {
        float acc2 = 0.f;
        int j = t & 31;
        for (int bb = t >> 5; bb < (int)gridDim.x; bb += 8) acc2 += g_part[bb * 32 + j];
        atomicAdd(&s30[j], acc2);
    }
    int w8 = t >> 5;
    #pragma unroll
    for (int it = 0; it < 4; it++) {
        int r = w8 + 8 * it;
        if (r < 30) {
            float p = 0.f;
            for (int k = lane; k < 512; k += 32) p += xs[k] * __ldg(W_lin1 + r * 512 + k);
            #pragma unroll
            for (int d = 16; d; d >>= 1) p += __shfl_down_sync(0xffffffffu, p, d);
            if (lane == 0) hi[r] = p;
        }
    }
    __syncthreads();
    if (t < 30) {
        hv[t] = s30[t] / (float)n + b2[t];     // a[0,0]
        float h = hi[t], a = 0.f;
        for (int i2 = 0; i2 < 64; i2++) {
            float s2 = 1.f / (1.f + expf(-w2c[i2] * h));
            a += w3c[i2] * s2;
        }
        hv[30 + t] = 1.f / (1.f + expf(-a));    // h_img
    }
    if (t >= 32 && t < 42) hv[60 + (t - 32)] = vocab[t - 32];
    __syncthreads();
    if (t < 2) {
        float l = 0.f;
        for (int k = 0; k < 70; k++) l += __ldg(W_lin4 + t * 70 + k) * hv[k];
        lg[t] = l;
    }
    __syncthreads();
    if (t < 2) {
        float m = fmaxf(lg[0], lg[1]);
        float lse = m + logf(expf(lg[0] - m) + expf(lg[1] - m));
        out[t] = lg[t] - lse;
    }
}

extern "C" void kernel_launch(void* const* d_in, const int* in_sizes, int n_in,
                              void* d_out, int out_size) {
    const float* x      = (const float*)d_in[0];
    const float* feat   = (const float*)d_in[1];
    const float* vocab  = (const float*)d_in[2];
    const int*   src    = (const int*)d_in[3];
    const int*   dst    = (const int*)d_in[4];
    const float* W_lin1 = (const float*)d_in[5];
    const float* w_c2   = (const float*)d_in[6];
    const float* w_c3   = (const float*)d_in[7];
    const float* W_lin4 = (const float*)d_in[8];
    const float* W1     = (const float*)d_in[9];
    const float* al1    = (const float*)d_in[10];
    const float* ar1    = (const float*)d_in[11];
    const float* b1     = (const float*)d_in[12];
    const float* W2     = (const float*)d_in[13];
    const float* al2    = (const float*)d_in[14];
    const float* ar2    = (const float*)d_in[15];
    const float* b2     = (const float*)d_in[16];

    int N = in_sizes[1] / 3;
    int E = in_sizes[3];
    int nodeBlocks = (N + 255) / 256;
    int edgeBlocks = (E + 255) / 256;

    void* zptr = nullptr;
    cudaGetSymbolAddress(&zptr, g_zbuf);
    // zero layer-1 accum (4N) plus den2/C planes (at fixed MAXN offsets) in one memset
    cudaMemsetAsync(zptr, 0, (size_t)(6 * MAXN) * sizeof(float), 0);

    k_node1<<<nodeBlocks, 256>>>(feat, W1, al1, ar1, N);
    k_edge1<<<edgeBlocks, 256>>>(src, dst, E);
    k_node2<<<nodeBlocks, 256>>>(W1, b1, W2, al2, ar2, N);
    k_edge2<<<edgeBlocks, 256>>>(src, dst, E);
    k_edge3<<<edgeBlocks, 256>>>(src, dst, E);
    k_node3f<<<NBLK3, 256>>>(N, x, vocab, W_lin1, w_c2, w_c3, W_lin4, b2, (float*)d_out);
}

// round 12
// speedup vs baseline: 1.7689x; 1.1324x over previous
#include <cuda_runtime.h>

// Problem-size capacities (N=100000, E=1000000 in this dataset)
#define MAXN 100352
#define MAXE 1000448
#define NBLK3 592            // 148 SMs * 4, node3 grid

// ---- device scratch (static: no allocations allowed) ----
__device__ float4 g_f4[MAXN];          // (f0, f1, f2, el1) per node
__device__ float  g_er1[MAXN];
// zeroed each call by one memset: [0,4N) layer1 accum (den,a0,a1,a2)*N ; [4N,5N) den2 ; [5N,6N) C
__device__ __align__(16) float g_zbuf[6 * MAXN];
__device__ float  g_we[MAXE];          // layer-2 edge weights (edge order)
__device__ float  g_z2[MAXN * 32];     // z2: N x 32 (30 used), coalesced rows
__device__ float  g_el2[MAXN];
__device__ float  g_er2[MAXN];
__device__ float  g_part[NBLK3 * 32];  // per-block partials
__device__ int    g_done;              // last-block counter; self-resetting

// -------- node pass 1: el1/er1 via collapsed 3-vectors cl = W1@al1, cr = W1@ar1 --------
__global__ void k_node1(const float* __restrict__ feat, const float* __restrict__ W1,
                        const float* __restrict__ al1, const float* __restrict__ ar1, int n) {
    __shared__ float sc[6];   // cl0,cr0,cl1,cr1,cl2,cr2
    int t = threadIdx.x, lane = t & 31;
    if (t < 192) {
        int which = t >> 5;              // 0..5
        int j = which >> 1;              // feat dim
        const float* a = (which & 1) ? ar1 : al1;
        float p = __ldg(W1 + j * 128 + lane) * __ldg(a + lane)
                + __ldg(W1 + j * 128 + lane + 32) * __ldg(a + lane + 32);
        #pragma unroll
        for (int d = 16; d; d >>= 1) p += __shfl_down_sync(0xffffffffu, p, d);
        if (lane == 0) sc[which] = p;
    }
    __syncthreads();
    int i = blockIdx.x * blockDim.x + t;
    if (i >= n) return;
    float f0 = feat[3 * i], f1 = feat[3 * i + 1], f2 = feat[3 * i + 2];
    float el = f0 * sc[0] + f1 * sc[2] + f2 * sc[4];
    float er = f0 * sc[1] + f1 * sc[3] + f2 * sc[5];
    g_f4[i] = make_float4(f0, f1, f2, el);
    g_er1[i] = er;
}

// -------- edge pass 1: {den1,acc0,acc1,acc2}[dst] += w*{1,f0,f1,f2} in ONE v4 RED --------
__global__ void k_edge1(const int* __restrict__ src, const int* __restrict__ dst, int e) {
    int i = blockIdx.x * blockDim.x + threadIdx.x;
    if (i >= e) return;
    int s = src[i], d = dst[i];
    float4 fs = __ldg(&g_f4[s]);
    float ee = fs.w + __ldg(&g_er1[d]);
    float w = __expf(ee > 0.f ? ee : 0.2f * ee);
    float* A = g_zbuf + 4 * d;           // 16B-aligned (g_zbuf is __align__(16))
    asm volatile("red.global.add.v4.f32 [%0], {%1, %2, %3, %4};"
                 :: "l"(A), "f"(w), "f"(w * fs.x), "f"(w * fs.y), "f"(w * fs.z)
                 : "memory");
}

// -------- node pass 2: h1 = acc/den ; r1 = relu(h1@W1 + b1) ; z2 = r1@W2 ; el2/er2 --------
__global__ void k_node2(const float* __restrict__ W1, const float* __restrict__ b1,
                        const float* __restrict__ W2, const float* __restrict__ al2,
                        const float* __restrict__ ar2, int n) {
    int i = blockIdx.x * blockDim.x + threadIdx.x;
    if (i >= n) return;
    const float4 A = *(const float4*)(g_zbuf + 4 * i);
    float inv = (A.x > 0.f) ? (1.f / A.x) : 0.f;
    float h0 = A.y * inv, h1 = A.z * inv, h2 = A.w * inv;
    float z2[30];
    #pragma unroll
    for (int j = 0; j < 30; j++) z2[j] = 0.f;
    for (int k = 0; k < 64; k++) {
        float r = h0 * __ldg(W1 + k) + h1 * __ldg(W1 + 128 + k) + h2 * __ldg(W1 + 256 + k)
                + __ldg(b1 + k);
        r = fmaxf(r, 0.f);
        const float* w2row = W2 + k * 60;
        #pragma unroll
        for (int j = 0; j < 30; j++) z2[j] += r * __ldg(w2row + j);
    }
    float el2 = 0.f, er2 = 0.f;
    float* zo = g_z2 + i * 32;
    #pragma unroll
    for (int j = 0; j < 30; j++) {
        zo[j] = z2[j];
        el2 += z2[j] * __ldg(al2 + j);
        er2 += z2[j] * __ldg(ar2 + j);
    }
    zo[30] = 0.f;
    zo[31] = 0.f;
    g_el2[i] = el2;
    g_er2[i] = er2;
}

// -------- edge pass 2: w = exp(leaky(el2[s]+er2[d])) ; store w ; den2[dst] += w --------
__global__ void k_edge2(const int* __restrict__ src, const int* __restrict__ dst, int e) {
    int i = blockIdx.x * blockDim.x + threadIdx.x;
    if (i >= e) return;
    int s = src[i], d = dst[i];
    float ee = __ldg(&g_el2[s]) + __ldg(&g_er2[d]);
    float w = __expf(ee > 0.f ? ee : 0.2f * ee);
    g_we[i] = w;
    atomicAdd(g_zbuf + 4 * MAXN + d, w);
}

// -------- edge pass 3: C[src] += w / den2[dst]  (w read coalesced) --------
__global__ void k_edge3(const int* __restrict__ src, const int* __restrict__ dst, int e) {
    int i = blockIdx.x * blockDim.x + threadIdx.x;
    if (i >= e) return;
    int s = src[i], d = dst[i];
    float w = g_we[i];
    float den = __ldg(g_zbuf + 4 * MAXN + d);   // >= w > 0 since this edge contributed
    atomicAdd(g_zbuf + 5 * MAXN + s, w / den);
}

// -------- node pass 3 + final: sum_s C[s]*z2[s] (lane-locked components), then tail ----
__global__ void k_node3f(int n,
                         const float* __restrict__ x, const float* __restrict__ vocab,
                         const float* __restrict__ W_lin1, const float* __restrict__ w2c,
                         const float* __restrict__ w3c, const float* __restrict__ W_lin4,
                         const float* __restrict__ b2, float* __restrict__ out) {
    __shared__ float bs[32];
    int t = threadIdx.x, lane = t & 31;
    if (t < 32) bs[t] = 0.f;
    __syncthreads();
    const float* C = g_zbuf + 5 * MAXN;
    float acc = 0.f;
    int total = n * 32;
    // stride is a multiple of 32 -> each lane keeps a fixed component j = lane
    for (int i = blockIdx.x * blockDim.x + t; i < total; i += gridDim.x * blockDim.x) {
        int s = i >> 5;
        acc += __ldg(C + s) * __ldg(g_z2 + i);
    }
    atomicAdd(&bs[lane], acc);
    __syncthreads();
    if (t < 32) g_part[blockIdx.x * 32 + t] = bs[t];
    __threadfence();
    __shared__ int amLast;
    if (t == 0) amLast = (atomicAdd(&g_done, 1) == (int)gridDim.x - 1);
    __syncthreads();
    if (!amLast) return;

    // ---------------- final phase (single block, 256 threads) ----------------
    if (t == 0) g_done = 0;                    // restore invariant for next replay
    __shared__ float s30[32];
    __shared__ float hi[32];
    __shared__ float hv[72];
    __shared__ float xs[512];
    __shared__ float lg[2];
    if (t < 32) s30[t] = 0.f;
    xs[t] = __ldg(x + t);
    xs[t + 256] = __ldg(x + t + 256);
    __syncthreads();
    {
        float acc2 = 0.f;
        int j = t & 31;
        for (int bb = t >> 5; bb < (int)gridDim.x; bb += 8) acc2 += g_part[bb * 32 + j];
        atomicAdd(&s30[j], acc2);
    }
    int w8 = t >> 5;
    #pragma unroll
    for (int it = 0; it < 4; it++) {
        int r = w8 + 8 * it;
        if (r < 30) {
            float p = 0.f;
            for (int k = lane; k < 512; k += 32) p += xs[k] * __ldg(W_lin1 + r * 512 + k);
            #pragma unroll
            for (int d = 16; d; d >>= 1) p += __shfl_down_sync(0xffffffffu, p, d);
            if (lane == 0) hi[r] = p;
        }
    }
    __syncthreads();
    if (t < 30) {
        hv[t] = s30[t] / (float)n + b2[t];     // a[0,0]
        float h = hi[t], a = 0.f;
        for (int i2 = 0; i2 < 64; i2++) {
            float s2 = 1.f / (1.f + expf(-w2c[i2] * h));
            a += w3c[i2] * s2;
        }
        hv[30 + t] = 1.f / (1.f + expf(-a));    // h_img
    }
    if (t >= 32 && t < 42) hv[60 + (t - 32)] = vocab[t - 32];
    __syncthreads();
    if (t < 2) {
        float l = 0.f;
        for (int k = 0; k < 70; k++) l += __ldg(W_lin4 + t * 70 + k) * hv[k];
        lg[t] = l;
    }
    __syncthreads();
    if (t < 2) {
        float m = fmaxf(lg[0], lg[1]);
        float lse = m + logf(expf(lg[0] - m) + expf(lg[1] - m));
        out[t] = lg[t] - lse;
    }
}

extern "C" void kernel_launch(void* const* d_in, const int* in_sizes, int n_in,
                              void* d_out, int out_size) {
    const float* x      = (const float*)d_in[0];
    const float* feat   = (const float*)d_in[1];
    const float* vocab  = (const float*)d_in[2];
    const int*   src    = (const int*)d_in[3];
    const int*   dst    = (const int*)d_in[4];
    const float* W_lin1 = (const float*)d_in[5];
    const float* w_c2   = (const float*)d_in[6];
    const float* w_c3   = (const float*)d_in[7];
    const float* W_lin4 = (const float*)d_in[8];
    const float* W1     = (const float*)d_in[9];
    const float* al1    = (const float*)d_in[10];
    const float* ar1    = (const float*)d_in[11];
    const float* b1     = (const float*)d_in[12];
    const float* W2     = (const float*)d_in[13];
    const float* al2    = (const float*)d_in[14];
    const float* ar2    = (const float*)d_in[15];
    const float* b2     = (const float*)d_in[16];

    int N = in_sizes[1] / 3;
    int E = in_sizes[3];
    int nodeBlocks = (N + 255) / 256;
    int edgeBlocks = (E + 255) / 256;

    void* zptr = nullptr;
    cudaGetSymbolAddress(&zptr, g_zbuf);
    // zero layer-1 accum (4N) plus den2/C planes (at fixed MAXN offsets) in one memset
    cudaMemsetAsync(zptr, 0, (size_t)(6 * MAXN) * sizeof(float), 0);

    k_node1<<<nodeBlocks, 256>>>(feat, W1, al1, ar1, N);
    k_edge1<<<edgeBlocks, 256>>>(src, dst, E);
    k_node2<<<nodeBlocks, 256>>>(W1, b1, W2, al2, ar2, N);
    k_edge2<<<edgeBlocks, 256>>>(src, dst, E);
    k_edge3<<<edgeBlocks, 256>>>(src, dst, E);
    k_node3f<<<NBLK3, 256>>>(N, x, vocab, W_lin1, w_c2, w_c3, W_lin4, b2, (float*)d_out);
}